// round 3
// baseline (speedup 1.0000x reference)
#include <cuda_runtime.h>
#include <cstdint>

#define T_LEN 2048
#define F_DIM 32
#define B_TOT 512
#define BT    (B_TOT * T_LEN)          // 1,048,576 rows

typedef unsigned long long U;          // packed f32x2 carrier

// ---------------- scratch (__device__ globals: no allocation allowed) -------
__device__ float g_gx[(size_t)BT * 4 * F_DIM];   // [B][T][4][F]  536 MB
__device__ float g_h [(size_t)BT * F_DIM];       // [B][T][F]     134 MB

// ---------------- packed fp32x2 helpers ------------------------------------
__device__ __forceinline__ U ffma2(U a, U b, U c) {
    U d; asm("fma.rn.f32x2 %0, %1, %2, %3;" : "=l"(d) : "l"(a), "l"(b), "l"(c));
    return d;
}
__device__ __forceinline__ U pack2(float lo, float hi) {
    U d; asm("mov.b64 %0, {%1, %2};" : "=l"(d) : "f"(lo), "f"(hi));
    return d;
}
__device__ __forceinline__ float2 unpk(U d) {
    float2 r; asm("mov.b64 {%0, %1}, %2;" : "=f"(r.x), "=f"(r.y) : "l"(d));
    return r;
}

// ---------------- activations (proven 1.4e-7 end-to-end) --------------------
__device__ __forceinline__ float sig_a(float x) {
    float e = __expf(-x);
    return __fdividef(1.0f, 1.0f + e);
}
__device__ __forceinline__ float tanh_a(float x) {
    x = fminf(15.0f, fmaxf(-15.0f, x));
    float e = __expf(-2.0f * x);
    return __fdividef(1.0f - e, 1.0f + e);
}

// ============================================================================
// K1: gx[b][t][g][f] = bias[g*32+f] + dot(W_ih[g*32+f,:], x[b][t][:])
//     warp = gate, 4 rows per iteration, no CTA barriers.
// ============================================================================
__global__ void __launch_bounds__(128)
k1_input_gemm(const float* __restrict__ x,
              const float* __restrict__ W_ih,
              const float* __restrict__ b_ih,
              const float* __restrict__ b_hh)
{
    __shared__ __align__(16) float xs[4][4][F_DIM];   // [warp][rowi][f]
    const int w = threadIdx.x >> 5;     // gate
    const int f = threadIdx.x & 31;     // feature

    U wih[16];
    {
        const U* p = (const U*)(W_ih + (size_t)(w * F_DIM + f) * F_DIM);
#pragma unroll
        for (int j = 0; j < 16; j++) wih[j] = p[j];
    }
    const float bias = b_ih[w * F_DIM + f] + b_hh[w * F_DIM + f];

    const int stride = gridDim.x * 4;
    int base = blockIdx.x * 4;

    float xr[4];
#pragma unroll
    for (int i = 0; i < 4; i++) xr[i] = x[(size_t)(base + i) * F_DIM + f];

    while (base < BT) {
#pragma unroll
        for (int i = 0; i < 4; i++) xs[w][i][f] = xr[i];
        __syncwarp();

        const int nb = base + stride;
        if (nb < BT) {
#pragma unroll
            for (int i = 0; i < 4; i++) xr[i] = x[(size_t)(nb + i) * F_DIM + f];
        }

#pragma unroll
        for (int i = 0; i < 4; i++) {
            const ulonglong2* xp = (const ulonglong2*)&xs[w][i][0];  // 8 x 16B
            U a0 = pack2(bias, 0.0f);
            U a1 = pack2(0.0f, 0.0f);
#pragma unroll
            for (int q = 0; q < 8; q++) {
                ulonglong2 v = xp[q];
                a0 = ffma2(wih[2 * q],     v.x, a0);
                a1 = ffma2(wih[2 * q + 1], v.y, a1);
            }
            float2 u0 = unpk(a0), u1 = unpk(a1);
            g_gx[(size_t)(base + i) * 128 + w * F_DIM + f] =
                (u0.x + u1.x) + (u0.y + u1.y);
        }
        __syncwarp();   // WAR: all reads of xs done before next stage
        base = nb;
    }
}

// ============================================================================
// K2: recurrence. warp = batch, lane = feature. Lane owns all 4 gates of its
//     feature -> update is lane-local. Double-buffered h, 1 syncwarp/step.
// ============================================================================
__global__ void __launch_bounds__(32)
k2_recurrence(const float* __restrict__ W_hh)
{
    __shared__ __align__(16) float hs[2][F_DIM];
    const int f = threadIdx.x;
    const int b = blockIdx.x;

    U whh[4][16];
#pragma unroll
    for (int g = 0; g < 4; g++) {
        const U* p = (const U*)(W_hh + (size_t)(g * F_DIM + f) * F_DIM);
#pragma unroll
        for (int j = 0; j < 16; j++) whh[g][j] = p[j];
    }

    const float* gp = g_gx + (size_t)b * T_LEN * 128;
    float*       hp = g_h  + (size_t)b * T_LEN * F_DIM;

    hs[0][f] = 0.0f;
    float c = 0.0f;

    float p0[4], p1[4];
#pragma unroll
    for (int g = 0; g < 4; g++) {
        p0[g] = gp[g * F_DIM + f];
        p1[g] = gp[128 + g * F_DIM + f];
    }
    __syncwarp();

    for (int t = 0; t < T_LEN; t++) {
        float cur[4];
#pragma unroll
        for (int g = 0; g < 4; g++) { cur[g] = p0[g]; p0[g] = p1[g]; }
        if (t + 2 < T_LEN) {
#pragma unroll
            for (int g = 0; g < 4; g++)
                p1[g] = gp[(size_t)(t + 2) * 128 + g * F_DIM + f];
        }

        const ulonglong2* hb = (const ulonglong2*)&hs[t & 1][0];  // 8 x 16B
        U a[4];
#pragma unroll
        for (int g = 0; g < 4; g++) a[g] = pack2(0.0f, 0.0f);
#pragma unroll
        for (int q = 0; q < 8; q++) {
            ulonglong2 v = hb[q];
#pragma unroll
            for (int g = 0; g < 4; g++) a[g] = ffma2(whh[g][2 * q],     v.x, a[g]);
#pragma unroll
            for (int g = 0; g < 4; g++) a[g] = ffma2(whh[g][2 * q + 1], v.y, a[g]);
        }
        float pre[4];
#pragma unroll
        for (int g = 0; g < 4; g++) {
            float2 u = unpk(a[g]);
            pre[g] = cur[g] + (u.x + u.y);
        }

        float gi = sig_a(pre[0]);
        float gf = sig_a(pre[1]);
        float gg = tanh_a(pre[2]);
        float go = sig_a(pre[3]);
        c = gf * c + gi * gg;
        float h = go * tanh_a(c);

        hs[(t + 1) & 1][f] = h;
        hp[(size_t)t * F_DIM + f] = h;
        __syncwarp();
    }
}

// ============================================================================
// K3: out[bt][f] = tanh(b_lin[f] + sum_j W_lin[f][2j]*h[bt][j]
//                                 + W_lin[f][2j+1]*x[bt][j])
//     warp = row-stream, z pairs (h_j, x_j) match consecutive W_lin pairs.
// ============================================================================
__global__ void __launch_bounds__(256)
k3_output(const float* __restrict__ x,
          const float* __restrict__ W_lin,
          const float* __restrict__ b_lin,
          float* __restrict__ out)
{
    __shared__ __align__(16) float2 zs[8][2][F_DIM];   // [warp][rowi][j]
    const int w = threadIdx.x >> 5;
    const int f = threadIdx.x & 31;

    U wl[32];
    {
        const U* p = (const U*)(W_lin + (size_t)f * 2 * F_DIM);
#pragma unroll
        for (int j = 0; j < 32; j++) wl[j] = p[j];
    }
    const float ob = b_lin[f];

    const int wid    = blockIdx.x * 8 + w;
    const int stride = gridDim.x * 8 * 2;
    int base = wid * 2;

    float hr[2], xr[2];
#pragma unroll
    for (int i = 0; i < 2; i++) {
        hr[i] = g_h[(size_t)(base + i) * F_DIM + f];
        xr[i] = x  [(size_t)(base + i) * F_DIM + f];
    }

    while (base < BT) {
#pragma unroll
        for (int i = 0; i < 2; i++) zs[w][i][f] = make_float2(hr[i], xr[i]);
        __syncwarp();

        const int nb = base + stride;
        if (nb < BT) {
#pragma unroll
            for (int i = 0; i < 2; i++) {
                hr[i] = g_h[(size_t)(nb + i) * F_DIM + f];
                xr[i] = x  [(size_t)(nb + i) * F_DIM + f];
            }
        }

#pragma unroll
        for (int i = 0; i < 2; i++) {
            const ulonglong2* zp = (const ulonglong2*)&zs[w][i][0];  // 16 x 16B
            U a0 = pack2(ob, 0.0f);
            U a1 = pack2(0.0f, 0.0f);
#pragma unroll
            for (int q = 0; q < 16; q++) {
                ulonglong2 v = zp[q];
                a0 = ffma2(wl[2 * q],     v.x, a0);
                a1 = ffma2(wl[2 * q + 1], v.y, a1);
            }
            float2 u0 = unpk(a0), u1 = unpk(a1);
            float s = (u0.x + u1.x) + (u0.y + u1.y);
            out[(size_t)(base + i) * F_DIM + f] = tanh_a(s);
        }
        __syncwarp();
        base = nb;
    }
}

// ============================================================================
extern "C" void kernel_launch(void* const* d_in, const int* in_sizes, int n_in,
                              void* d_out, int out_size)
{
    const float* x     = (const float*)d_in[0];
    const float* W_ih  = (const float*)d_in[1];
    const float* W_hh  = (const float*)d_in[2];
    const float* b_ih  = (const float*)d_in[3];
    const float* b_hh  = (const float*)d_in[4];
    const float* W_lin = (const float*)d_in[5];
    const float* b_lin = (const float*)d_in[6];
    float* out = (float*)d_out;

    k1_input_gemm<<<2048, 128>>>(x, W_ih, b_ih, b_hh);
    k2_recurrence<<<B_TOT, 32>>>(W_hh);
    k3_output<<<2048, 256>>>(x, W_lin, b_lin, out);
}

// round 4
// speedup vs baseline: 1.2117x; 1.2117x over previous
#include <cuda_runtime.h>
#include <cstdint>

#define T_LEN 2048
#define F_DIM 32
#define B_TOT 512
#define BT    (B_TOT * T_LEN)          // 1,048,576 rows

typedef unsigned long long U;          // packed f32x2 carrier

// ---------------- scratch (__device__ globals: no allocation allowed) -------
__device__ float g_gx[(size_t)BT * 4 * F_DIM];   // [B][T][4][F]  536 MB (bias included)
__device__ float g_h [(size_t)BT * F_DIM];       // [B][T][F]     134 MB

// ---------------- packed fp32x2 helpers ------------------------------------
__device__ __forceinline__ U ffma2(U a, U b, U c) {
    U d; asm("fma.rn.f32x2 %0, %1, %2, %3;" : "=l"(d) : "l"(a), "l"(b), "l"(c));
    return d;
}
__device__ __forceinline__ U pack2(float lo, float hi) {
    U d; asm("mov.b64 %0, {%1, %2};" : "=l"(d) : "f"(lo), "f"(hi));
    return d;
}
__device__ __forceinline__ float2 unpk(U d) {
    float2 r; asm("mov.b64 {%0, %1}, %2;" : "=f"(r.x), "=f"(r.y) : "l"(d));
    return r;
}

// ---------------- activations (proven 1.4e-7 end-to-end) --------------------
__device__ __forceinline__ float sig_a(float x) {
    float e = __expf(-x);
    return __fdividef(1.0f, 1.0f + e);
}
__device__ __forceinline__ float tanh_a(float x) {
    x = fminf(15.0f, fmaxf(-15.0f, x));
    float e = __expf(-2.0f * x);
    return __fdividef(1.0f - e, 1.0f + e);
}

// ============================================================================
// K1: gx[row][g][f] = bias + dot(W_ih[g*32+f,:], x[row][:])
//     Warp owns 2 gates; x read via uniform LDG.128 broadcast (no smem/sync).
//     8192 warps x 256 rows, ring-2 row prefetch.
// ============================================================================
__global__ void __launch_bounds__(128, 1)
k1_input_gemm(const float* __restrict__ x,
              const float* __restrict__ W_ih,
              const float* __restrict__ b_ih,
              const float* __restrict__ b_hh)
{
    const int w  = threadIdx.x >> 5;
    const int f  = threadIdx.x & 31;
    const int gw = blockIdx.x * 4 + w;        // global warp 0..8191
    const int g0 = (gw & 1) * 2;              // gates {0,1} or {2,3}
    const int base = (gw >> 1) * 256;         // 256 rows per warp-pair

    U wa[16], wb[16];
    {
        const U* pa = (const U*)(W_ih + (size_t)(g0 * 32 + f) * 32);
        const U* pb = (const U*)(W_ih + (size_t)((g0 + 1) * 32 + f) * 32);
#pragma unroll
        for (int j = 0; j < 16; j++) { wa[j] = pa[j]; wb[j] = pb[j]; }
    }
    const float ba = b_ih[g0 * 32 + f] + b_hh[g0 * 32 + f];
    const float bb = b_ih[(g0 + 1) * 32 + f] + b_hh[(g0 + 1) * 32 + f];

    ulonglong2 B0[8], B1[8];
    {
        const ulonglong2* p0 = (const ulonglong2*)(x + (size_t)base * F_DIM);
        const ulonglong2* p1 = (const ulonglong2*)(x + (size_t)(base + 1) * F_DIM);
#pragma unroll
        for (int q = 0; q < 8; q++) { B0[q] = p0[q]; B1[q] = p1[q]; }
    }

    for (int r = 0; r < 256; r += 2) {
        // ---- row base+r from B0 ----
        {
            U a0 = pack2(ba, 0.0f), a1 = pack2(0.0f, 0.0f);
            U c0 = pack2(bb, 0.0f), c1 = pack2(0.0f, 0.0f);
#pragma unroll
            for (int q = 0; q < 8; q++) {
                ulonglong2 v = B0[q];
                a0 = ffma2(wa[2 * q],     v.x, a0);
                a1 = ffma2(wa[2 * q + 1], v.y, a1);
                c0 = ffma2(wb[2 * q],     v.x, c0);
                c1 = ffma2(wb[2 * q + 1], v.y, c1);
            }
            float2 u0 = unpk(a0), u1 = unpk(a1), u2 = unpk(c0), u3 = unpk(c1);
            const size_t ro = (size_t)(base + r) * 128;
            g_gx[ro + g0 * 32 + f]       = (u0.x + u1.x) + (u0.y + u1.y);
            g_gx[ro + (g0 + 1) * 32 + f] = (u2.x + u3.x) + (u2.y + u3.y);
        }
        {   // prefetch r+2 -> B0
            int nr = min(base + r + 2, BT - 1);
            const ulonglong2* p = (const ulonglong2*)(x + (size_t)nr * F_DIM);
#pragma unroll
            for (int q = 0; q < 8; q++) B0[q] = p[q];
        }
        // ---- row base+r+1 from B1 ----
        {
            U a0 = pack2(ba, 0.0f), a1 = pack2(0.0f, 0.0f);
            U c0 = pack2(bb, 0.0f), c1 = pack2(0.0f, 0.0f);
#pragma unroll
            for (int q = 0; q < 8; q++) {
                ulonglong2 v = B1[q];
                a0 = ffma2(wa[2 * q],     v.x, a0);
                a1 = ffma2(wa[2 * q + 1], v.y, a1);
                c0 = ffma2(wb[2 * q],     v.x, c0);
                c1 = ffma2(wb[2 * q + 1], v.y, c1);
            }
            float2 u0 = unpk(a0), u1 = unpk(a1), u2 = unpk(c0), u3 = unpk(c1);
            const size_t ro = (size_t)(base + r + 1) * 128;
            g_gx[ro + g0 * 32 + f]       = (u0.x + u1.x) + (u0.y + u1.y);
            g_gx[ro + (g0 + 1) * 32 + f] = (u2.x + u3.x) + (u2.y + u3.y);
        }
        {   // prefetch r+3 -> B1
            int nr = min(base + r + 3, BT - 1);
            const ulonglong2* p = (const ulonglong2*)(x + (size_t)nr * F_DIM);
#pragma unroll
            for (int q = 0; q < 8; q++) B1[q] = p[q];
        }
    }
}

// ============================================================================
// K2: recurrence. 4 warps/CTA (one batch each -> one warp per SMSP), grid=128.
//     Lane owns all 4 gates of its feature. 4-deep gx register ring,
//     4x-unrolled time loop (static ring & h-buffer indices), 1 syncwarp/step.
// ============================================================================
__global__ void __launch_bounds__(128, 1)
k2_recurrence(const float* __restrict__ W_hh)
{
    __shared__ __align__(16) float hs[4][2][F_DIM];
    const int w = threadIdx.x >> 5;
    const int f = threadIdx.x & 31;
    const int b = blockIdx.x * 4 + w;

    U whh[4][16];
#pragma unroll
    for (int g = 0; g < 4; g++) {
        const U* p = (const U*)(W_hh + (size_t)(g * F_DIM + f) * F_DIM);
#pragma unroll
        for (int j = 0; j < 16; j++) whh[g][j] = p[j];
    }

    const float* gp = g_gx + (size_t)b * T_LEN * 128;
    float*       hp = g_h  + (size_t)b * T_LEN * F_DIM;

    hs[w][0][f] = 0.0f;
    float c = 0.0f;

    float R[4][4];                       // 4-step gx ring
#pragma unroll
    for (int u = 0; u < 4; u++)
#pragma unroll
        for (int g = 0; g < 4; g++)
            R[u][g] = gp[u * 128 + g * F_DIM + f];
    __syncwarp();

    for (int tb = 0; tb < T_LEN; tb += 4) {
#pragma unroll
        for (int u = 0; u < 4; u++) {
            const int t = tb + u;
            float cur[4];
#pragma unroll
            for (int g = 0; g < 4; g++) cur[g] = R[u][g];
            {   // refill ring slot u with step t+4 (clamped; tail loads unused)
                const int pt = min(t + 4, T_LEN - 1);
#pragma unroll
                for (int g = 0; g < 4; g++)
                    R[u][g] = gp[(size_t)pt * 128 + g * F_DIM + f];
            }

            const ulonglong2* hb = (const ulonglong2*)&hs[w][u & 1][0];
            U a0[4], a1[4];
#pragma unroll
            for (int g = 0; g < 4; g++) {
                a0[g] = pack2(cur[g], 0.0f);
                a1[g] = pack2(0.0f, 0.0f);
            }
#pragma unroll
            for (int q = 0; q < 8; q++) {
                ulonglong2 v = hb[q];
#pragma unroll
                for (int g = 0; g < 4; g++) a0[g] = ffma2(whh[g][2 * q],     v.x, a0[g]);
#pragma unroll
                for (int g = 0; g < 4; g++) a1[g] = ffma2(whh[g][2 * q + 1], v.y, a1[g]);
            }
            float pre[4];
#pragma unroll
            for (int g = 0; g < 4; g++) {
                float2 u0 = unpk(a0[g]), u1 = unpk(a1[g]);
                pre[g] = (u0.x + u1.x) + (u0.y + u1.y);
            }

            float gi = sig_a(pre[0]);
            float gf = sig_a(pre[1]);
            float gg = tanh_a(pre[2]);
            float go = sig_a(pre[3]);
            c = gf * c + gi * gg;
            float h = go * tanh_a(c);

            hs[w][(u & 1) ^ 1][f] = h;
            hp[(size_t)t * F_DIM + f] = h;
            __syncwarp();
        }
    }
}

// ============================================================================
// K3: out[row][f] = tanh(b_lin[f] + sum_j W[f][2j]*h[row][j] + W[f][2j+1]*x[row][j])
//     Warp-private: uniform LDG broadcast of h/x rows; W_lin pre-split into
//     even/odd packed pairs. 8192 warps x 128 rows, ring-2 prefetch.
// ============================================================================
__global__ void __launch_bounds__(128, 1)
k3_output(const float* __restrict__ x,
          const float* __restrict__ W_lin,
          const float* __restrict__ b_lin,
          float* __restrict__ out)
{
    const int w  = threadIdx.x >> 5;
    const int f  = threadIdx.x & 31;
    const int gw = blockIdx.x * 4 + w;       // 0..8191
    const int base = gw * 128;               // 128 rows per warp

    U wlh[16], wlx[16];                      // pair m: (W[4m], W[4m+2]) / (W[4m+1], W[4m+3])
    {
        const float* wr = W_lin + (size_t)f * 64;
#pragma unroll
        for (int m = 0; m < 16; m++) {
            wlh[m] = pack2(wr[4 * m],     wr[4 * m + 2]);
            wlx[m] = pack2(wr[4 * m + 1], wr[4 * m + 3]);
        }
    }
    const float ob = b_lin[f];

    ulonglong2 H0[8], X0[8], H1[8], X1[8];
    {
        const ulonglong2* ph0 = (const ulonglong2*)(g_h + (size_t)base * F_DIM);
        const ulonglong2* px0 = (const ulonglong2*)(x   + (size_t)base * F_DIM);
        const ulonglong2* ph1 = (const ulonglong2*)(g_h + (size_t)(base + 1) * F_DIM);
        const ulonglong2* px1 = (const ulonglong2*)(x   + (size_t)(base + 1) * F_DIM);
#pragma unroll
        for (int q = 0; q < 8; q++) { H0[q] = ph0[q]; X0[q] = px0[q]; H1[q] = ph1[q]; X1[q] = px1[q]; }
    }

    for (int r = 0; r < 128; r += 2) {
        // ---- row base+r ----
        {
            U a0 = pack2(ob, 0.0f), a1 = pack2(0.0f, 0.0f);
            U a2 = pack2(0.0f, 0.0f), a3 = pack2(0.0f, 0.0f);
#pragma unroll
            for (int q = 0; q < 8; q++) {
                ulonglong2 hv = H0[q], xv = X0[q];
                a0 = ffma2(wlh[2 * q],     hv.x, a0);
                a1 = ffma2(wlh[2 * q + 1], hv.y, a1);
                a2 = ffma2(wlx[2 * q],     xv.x, a2);
                a3 = ffma2(wlx[2 * q + 1], xv.y, a3);
            }
            float2 u0 = unpk(a0), u1 = unpk(a1), u2 = unpk(a2), u3 = unpk(a3);
            float s = ((u0.x + u1.x) + (u0.y + u1.y)) + ((u2.x + u3.x) + (u2.y + u3.y));
            out[(size_t)(base + r) * F_DIM + f] = tanh_a(s);
        }
        {   // prefetch r+2
            int nr = min(base + r + 2, BT - 1);
            const ulonglong2* ph = (const ulonglong2*)(g_h + (size_t)nr * F_DIM);
            const ulonglong2* px = (const ulonglong2*)(x   + (size_t)nr * F_DIM);
#pragma unroll
            for (int q = 0; q < 8; q++) { H0[q] = ph[q]; X0[q] = px[q]; }
        }
        // ---- row base+r+1 ----
        {
            U a0 = pack2(ob, 0.0f), a1 = pack2(0.0f, 0.0f);
            U a2 = pack2(0.0f, 0.0f), a3 = pack2(0.0f, 0.0f);
#pragma unroll
            for (int q = 0; q < 8; q++) {
                ulonglong2 hv = H1[q], xv = X1[q];
                a0 = ffma2(wlh[2 * q],     hv.x, a0);
                a1 = ffma2(wlh[2 * q + 1], hv.y, a1);
                a2 = ffma2(wlx[2 * q],     xv.x, a2);
                a3 = ffma2(wlx[2 * q + 1], xv.y, a3);
            }
            float2 u0 = unpk(a0), u1 = unpk(a1), u2 = unpk(a2), u3 = unpk(a3);
            float s = ((u0.x + u1.x) + (u0.y + u1.y)) + ((u2.x + u3.x) + (u2.y + u3.y));
            out[(size_t)(base + r + 1) * F_DIM + f] = tanh_a(s);
        }
        {   // prefetch r+3
            int nr = min(base + r + 3, BT - 1);
            const ulonglong2* ph = (const ulonglong2*)(g_h + (size_t)nr * F_DIM);
            const ulonglong2* px = (const ulonglong2*)(x   + (size_t)nr * F_DIM);
#pragma unroll
            for (int q = 0; q < 8; q++) { H1[q] = ph[q]; X1[q] = px[q]; }
        }
    }
}

// ============================================================================
extern "C" void kernel_launch(void* const* d_in, const int* in_sizes, int n_in,
                              void* d_out, int out_size)
{
    const float* x     = (const float*)d_in[0];
    const float* W_ih  = (const float*)d_in[1];
    const float* W_hh  = (const float*)d_in[2];
    const float* b_ih  = (const float*)d_in[3];
    const float* b_hh  = (const float*)d_in[4];
    const float* W_lin = (const float*)d_in[5];
    const float* b_lin = (const float*)d_in[6];
    float* out = (float*)d_out;

    k1_input_gemm<<<2048, 128>>>(x, W_ih, b_ih, b_hh);   // 8192 warps, 2 gates each
    k2_recurrence<<<128, 128>>>(W_hh);                    // 512 batch-warps, 1/SMSP
    k3_output<<<2048, 128>>>(x, W_lin, b_lin, out);       // 8192 warps
}

// round 5
// speedup vs baseline: 1.4152x; 1.1680x over previous
#include <cuda_runtime.h>
#include <cstdint>

#define T_LEN 2048
#define F_DIM 32
#define B_TOT 512
#define NBAT  4                        // batches per CTA (team of 2 warps each)

typedef unsigned long long U;          // packed f32x2 carrier

// ---------------- packed fp32x2 helpers ------------------------------------
__device__ __forceinline__ U ffma2(U a, U b, U c) {
    U d; asm("fma.rn.f32x2 %0, %1, %2, %3;" : "=l"(d) : "l"(a), "l"(b), "l"(c));
    return d;
}
__device__ __forceinline__ U pack2(float lo, float hi) {
    U d; asm("mov.b64 %0, {%1, %2};" : "=l"(d) : "f"(lo), "f"(hi));
    return d;
}
__device__ __forceinline__ float2 unpk(U d) {
    float2 r; asm("mov.b64 {%0, %1}, %2;" : "=f"(r.x), "=f"(r.y) : "l"(d));
    return r;
}

// ---------------- activations (proven 1.4e-7 end-to-end) --------------------
__device__ __forceinline__ float sig_a(float x) {
    float e = __expf(-x);
    return __fdividef(1.0f, 1.0f + e);
}
__device__ __forceinline__ float tanh_a(float x) {
    x = fminf(15.0f, fmaxf(-15.0f, x));
    float e = __expf(-2.0f * x);
    return __fdividef(1.0f - e, 1.0f + e);
}

// ============================================================================
// Fully fused LSTM + output linear. CTA = 4 batches x (warp A + warp B).
//   warps 0..3  = A (batch = wid):    gates i,f,g + c/h chain, stages h
//   warps 4..7  = B (batch = wid-4):  gate o + output linear + x staging
// z row per batch: 64 floats interleaved (h_j, x_j). Double-buffered.
// ============================================================================
__global__ void __launch_bounds__(256, 1)
lstm_all(const float* __restrict__ x,
         const float* __restrict__ W_ih,
         const float* __restrict__ W_hh,
         const float* __restrict__ b_ih,
         const float* __restrict__ b_hh,
         const float* __restrict__ W_lin,
         const float* __restrict__ b_lin,
         float* __restrict__ out)
{
    __shared__ __align__(16) float zb[NBAT][2][2 * F_DIM];   // (h,x) interleaved
    __shared__ float go_sm[NBAT][2][F_DIM];                  // o-gate activation

    const int w     = threadIdx.x >> 5;
    const int f     = threadIdx.x & 31;
    const bool roleB = (w >= 4);
    const int lb    = w & 3;
    const int b     = blockIdx.x * NBAT + lb;

    const float* xp = x   + (size_t)b * T_LEN * F_DIM + f;
    float*       op = out + (size_t)b * T_LEN * F_DIM + f;

    // ------------------- per-role register state ---------------------------
    U wcA[3][32];            // A: gates i,f,g  — pairs (W_hh[j], W_ih[j])
    U woB[32];               // B: gate o pairs
    U wl2[32];               // B: W_lin pairs (W[f][2j], W[f][2j+1])
    float biasA0 = 0.f, biasA1 = 0.f, biasA2 = 0.f;
    float biasO = 0.f, ob = 0.f;
    float xr[4];             // B: x ring (x_{t+1..t+4})
    float c = 0.0f;          // A: cell state
    float prev_y = 0.0f;     // B: carried x-part of out

    if (!roleB) {
#pragma unroll
        for (int g = 0; g < 3; g++) {
            const float* ph = W_hh + (size_t)(g * F_DIM + f) * F_DIM;
            const float* pi = W_ih + (size_t)(g * F_DIM + f) * F_DIM;
#pragma unroll
            for (int j = 0; j < 32; j++) wcA[g][j] = pack2(ph[j], pi[j]);
        }
        biasA0 = b_ih[0 * F_DIM + f] + b_hh[0 * F_DIM + f];
        biasA1 = b_ih[1 * F_DIM + f] + b_hh[1 * F_DIM + f];
        biasA2 = b_ih[2 * F_DIM + f] + b_hh[2 * F_DIM + f];
        zb[lb][0][2 * f] = 0.0f;                 // h_{-1} = 0
    } else {
        const float* ph = W_hh + (size_t)(3 * F_DIM + f) * F_DIM;
        const float* pi = W_ih + (size_t)(3 * F_DIM + f) * F_DIM;
#pragma unroll
        for (int j = 0; j < 32; j++) woB[j] = pack2(ph[j], pi[j]);
        biasO = b_ih[3 * F_DIM + f] + b_hh[3 * F_DIM + f];
        const float* pl = W_lin + (size_t)f * 2 * F_DIM;
#pragma unroll
        for (int j = 0; j < 32; j++) wl2[j] = pack2(pl[2 * j], pl[2 * j + 1]);
        ob = b_lin[f];
        zb[lb][0][2 * f + 1] = xp[0];            // stage x_0
#pragma unroll
        for (int k = 0; k < 4; k++) xr[k] = xp[(size_t)(k + 1) * F_DIM];
    }
    __syncthreads();   // zb[*][0] = (0, x_0) published

    for (int tb = 0; tb < T_LEN; tb += 4) {
#pragma unroll
        for (int u = 0; u < 4; u++) {
            const int t  = tb + u;
            const int s  = u & 1;
            const int ns = s ^ 1;
            const ulonglong2* zr = (const ulonglong2*)&zb[lb][s][0];  // 16 x 16B

            // =========== phase 1: gate chains ===========
            float gi, gf, gg;                 // A outputs
            U al0, al1;                       // B out-linear accumulators
            if (!roleB) {
                U a00 = pack2(biasA0, 0.f), a01 = pack2(0.f, 0.f);
                U a10 = pack2(biasA1, 0.f), a11 = pack2(0.f, 0.f);
                U a20 = pack2(biasA2, 0.f), a21 = pack2(0.f, 0.f);
#pragma unroll
                for (int q = 0; q < 16; q++) {
                    ulonglong2 v = zr[q];
                    a00 = ffma2(wcA[0][2 * q],     v.x, a00);
                    a10 = ffma2(wcA[1][2 * q],     v.x, a10);
                    a20 = ffma2(wcA[2][2 * q],     v.x, a20);
                    a01 = ffma2(wcA[0][2 * q + 1], v.y, a01);
                    a11 = ffma2(wcA[1][2 * q + 1], v.y, a11);
                    a21 = ffma2(wcA[2][2 * q + 1], v.y, a21);
                }
                float2 u0 = unpk(a00), u1 = unpk(a01);
                float2 u2 = unpk(a10), u3 = unpk(a11);
                float2 u4 = unpk(a20), u5 = unpk(a21);
                gi = sig_a((u0.x + u1.x) + (u0.y + u1.y));
                gf = sig_a((u2.x + u3.x) + (u2.y + u3.y));
                gg = tanh_a((u4.x + u5.x) + (u4.y + u5.y));
            } else {
                U o0 = pack2(biasO, 0.f), o1 = pack2(0.f, 0.f);
                al0 = pack2(0.f, 0.f); al1 = pack2(0.f, 0.f);
#pragma unroll
                for (int q = 0; q < 16; q++) {
                    ulonglong2 v = zr[q];
                    o0  = ffma2(woB[2 * q],     v.x, o0);
                    al0 = ffma2(wl2[2 * q],     v.x, al0);
                    o1  = ffma2(woB[2 * q + 1], v.y, o1);
                    al1 = ffma2(wl2[2 * q + 1], v.y, al1);
                }
                float2 u0 = unpk(o0), u1 = unpk(o1);
                float go = sig_a((u0.x + u1.x) + (u0.y + u1.y));
                go_sm[lb][s][f] = go;
            }

            __syncthreads();   // go published; (drains STS)

            // =========== phase 2: state update / output ===========
            if (!roleB) {
                float go = go_sm[lb][s][f];
                c = gf * c + gi * gg;
                float h = go * tanh_a(c);
                zb[lb][ns][2 * f] = h;                    // h_t for step t+1
            } else {
                // finish out_{t-1}: .x halves = sum wlh*h_{t-1}; carried .y = x_{t-1} part
                float2 s0 = unpk(al0), s1 = unpk(al1);
                float sumh = s0.x + s1.x;
                float sumx = s0.y + s1.y;
                if (t > 0)
                    op[(size_t)(t - 1) * F_DIM] = tanh_a(prev_y + sumh + ob);
                prev_y = sumx;

                zb[lb][ns][2 * f + 1] = xr[u];            // stage x_{t+1}
                int pt = t + 5; if (pt > T_LEN - 1) pt = T_LEN - 1;
                xr[u] = xp[(size_t)pt * F_DIM];           // refill ring
            }

            __syncthreads();   // zb[ns] = (h_t, x_{t+1}) published
        }
    }

    // ---- epilogue: out_{T-1} (h_{T-1} is in zb[lb][0] .x halves) ----
    if (roleB) {
        const ulonglong2* zr = (const ulonglong2*)&zb[lb][0][0];
        U al0 = pack2(0.f, 0.f), al1 = pack2(0.f, 0.f);
#pragma unroll
        for (int q = 0; q < 16; q++) {
            ulonglong2 v = zr[q];
            al0 = ffma2(wl2[2 * q],     v.x, al0);
            al1 = ffma2(wl2[2 * q + 1], v.y, al1);
        }
        float2 s0 = unpk(al0), s1 = unpk(al1);
        float sumh = s0.x + s1.x;
        op[(size_t)(T_LEN - 1) * F_DIM] = tanh_a(prev_y + sumh + ob);
    }
}

// ============================================================================
extern "C" void kernel_launch(void* const* d_in, const int* in_sizes, int n_in,
                              void* d_out, int out_size)
{
    const float* x     = (const float*)d_in[0];
    const float* W_ih  = (const float*)d_in[1];
    const float* W_hh  = (const float*)d_in[2];
    const float* b_ih  = (const float*)d_in[3];
    const float* b_hh  = (const float*)d_in[4];
    const float* W_lin = (const float*)d_in[5];
    const float* b_lin = (const float*)d_in[6];
    float* out = (float*)d_out;

    lstm_all<<<B_TOT / NBAT, 256>>>(x, W_ih, W_hh, b_ih, b_hh, W_lin, b_lin, out);
}

// round 6
// speedup vs baseline: 1.6191x; 1.1440x over previous
#include <cuda_runtime.h>
#include <cstdint>

#define T_LEN 2048
#define F_DIM 32
#define B_TOT 512

typedef unsigned long long U;          // packed f32x2 carrier

// ---------------- packed fp32x2 helpers ------------------------------------
__device__ __forceinline__ U ffma2(U a, U b, U c) {
    U d; asm("fma.rn.f32x2 %0, %1, %2, %3;" : "=l"(d) : "l"(a), "l"(b), "l"(c));
    return d;
}
__device__ __forceinline__ U pack2(float lo, float hi) {
    U d; asm("mov.b64 %0, {%1, %2};" : "=l"(d) : "f"(lo), "f"(hi));
    return d;
}
__device__ __forceinline__ float2 unpk(U d) {
    float2 r; asm("mov.b64 {%0, %1}, %2;" : "=f"(r.x), "=f"(r.y) : "l"(d));
    return r;
}

// ---------------- activations (proven 1.4e-7 end-to-end) --------------------
__device__ __forceinline__ float sig_a(float x) {
    float e = __expf(-x);
    return __fdividef(1.0f, 1.0f + e);
}
__device__ __forceinline__ float tanh_a(float x) {
    x = fminf(15.0f, fmaxf(-15.0f, x));
    float e = __expf(-2.0f * x);
    return __fdividef(1.0f - e, 1.0f + e);
}

// ============================================================================
// Fully fused LSTM + output linear.
//   CTA = 1 batch, 4 warps (warp = gate i,f,g,o). grid = 512 -> 4 CTAs/SM,
//   4 independent batches per SMSP to hide chain/barrier latency.
//   Each warp also computes an 8-pair chunk of the output linear against the
//   same z=(h_{t-1},x_t) vector; warp 0 reduces partials -> out_{t-1};
//   warp 3 owns the c/h chain and z staging.
// ============================================================================
__global__ void __launch_bounds__(128, 4)
lstm_fused(const float* __restrict__ x,
           const float* __restrict__ W_ih,
           const float* __restrict__ W_hh,
           const float* __restrict__ b_ih,
           const float* __restrict__ b_hh,
           const float* __restrict__ W_lin,
           const float* __restrict__ b_lin,
           float* __restrict__ out)
{
    __shared__ __align__(16) float zb[2][2 * F_DIM];  // interleaved (h_j, x_j)
    __shared__ float g_sm[3][F_DIM];                  // activated gates i,f,g
    __shared__ float p_sm[4][F_DIM];                  // out-linear partials

    const int w = threadIdx.x >> 5;    // warp = gate
    const int f = threadIdx.x & 31;    // lane = feature
    const int b = blockIdx.x;          // batch

    // ---- gate weights: pair j = (W_hh[g,f,j], W_ih[g,f,j]) ----
    U wc[32];
    {
        const float* ph = W_hh + (size_t)(w * F_DIM + f) * F_DIM;
        const float* pi = W_ih + (size_t)(w * F_DIM + f) * F_DIM;
#pragma unroll
        for (int j = 0; j < 32; j++) wc[j] = pack2(ph[j], pi[j]);
    }
    const float bias = b_ih[w * F_DIM + f] + b_hh[w * F_DIM + f];

    // ---- out-linear chunk: pairs j = 8w .. 8w+7 ----
    U wl[8];
    {
        const float* pl = W_lin + (size_t)f * 2 * F_DIM + w * 16;
#pragma unroll
        for (int m = 0; m < 8; m++) wl[m] = pack2(pl[2 * m], pl[2 * m + 1]);
    }
    const float ob = b_lin[f];

    const float* xp = x   + (size_t)b * T_LEN * F_DIM + f;
    float*       op = out + (size_t)b * T_LEN * F_DIM + f;

    float c = 0.0f;          // warp 3: cell state
    float go = 0.0f;         // warp 3: o-gate act
    float prev_sx = 0.0f;    // per-warp carried x-part of out partial
    float xr[4];             // warp 3: x prefetch ring (x_{t+1..t+4})

    if (w == 3) {
        *(float2*)&zb[0][2 * f] = make_float2(0.0f, xp[0]);   // (h_{-1}=0, x_0)
#pragma unroll
        for (int k = 0; k < 4; k++) xr[k] = xp[(size_t)(k + 1) * F_DIM];
    }
    __syncthreads();

    for (int tb = 0; tb < T_LEN; tb += 4) {
#pragma unroll
        for (int u = 0; u < 4; u++) {
            const int t  = tb + u;
            const int s  = u & 1;
            const int ns = s ^ 1;
            const ulonglong2* zr = (const ulonglong2*)&zb[s][0];  // 16 x 16B uniform

            // ---------- phase 1: gate dot + out-linear chunk ----------
            U a0 = pack2(bias, 0.f), a1 = pack2(0.f, 0.f);
            U a2 = pack2(0.f, 0.f),  a3 = pack2(0.f, 0.f);
#pragma unroll
            for (int q = 0; q < 16; q += 2) {
                ulonglong2 v0 = zr[q];
                ulonglong2 v1 = zr[q + 1];
                a0 = ffma2(wc[2 * q],     v0.x, a0);
                a1 = ffma2(wc[2 * q + 1], v0.y, a1);
                a2 = ffma2(wc[2 * q + 2], v1.x, a2);
                a3 = ffma2(wc[2 * q + 3], v1.y, a3);
            }
            U o0 = pack2(0.f, 0.f), o1 = pack2(0.f, 0.f);
#pragma unroll
            for (int m = 0; m < 4; m++) {
                ulonglong2 v = zr[4 * w + m];         // uniform LDS (chunk reload)
                o0 = ffma2(wl[2 * m],     v.x, o0);
                o1 = ffma2(wl[2 * m + 1], v.y, o1);
            }

            float2 u0 = unpk(a0), u1 = unpk(a1), u2 = unpk(a2), u3 = unpk(a3);
            float pre = ((u0.x + u0.y) + (u1.x + u1.y))
                      + ((u2.x + u2.y) + (u3.x + u3.y));
            float act = (w == 2) ? tanh_a(pre) : sig_a(pre);
            if (w == 3) go = act;
            else        g_sm[w][f] = act;

            float2 s0 = unpk(o0), s1 = unpk(o1);
            float p = (s0.x + s1.x) + prev_sx;        // h-part(t-1) + x-part(t-1)
            prev_sx = s0.y + s1.y;                    // carry x-part(t)
            p_sm[w][f] = p;

            __syncthreads();   // BAR1: gates + partials published

            // ---------- phase 2: state update / output finish ----------
            if (w == 3) {
                float gi = g_sm[0][f];
                float gf = g_sm[1][f];
                float gg = g_sm[2][f];
                c = gf * c + gi * gg;
                float h = go * tanh_a(c);
                *(float2*)&zb[ns][2 * f] = make_float2(h, xr[u]);  // (h_t, x_{t+1})
                int pt = t + 5; if (pt > T_LEN - 1) pt = T_LEN - 1;
                xr[u] = xp[(size_t)pt * F_DIM];
            } else if (w == 0 && t > 0) {
                float sum = p + p_sm[1][f] + p_sm[2][f] + p_sm[3][f] + ob;
                op[(size_t)(t - 1) * F_DIM] = tanh_a(sum);
            }

            __syncthreads();   // BAR2: zb[ns] published; p_sm free for reuse
        }
    }

    // ---- epilogue: out_{T-1} from zb[0] = (h_{T-1}, junk) ----
    {
        const ulonglong2* zr = (const ulonglong2*)&zb[0][0];
        U o0 = pack2(0.f, 0.f), o1 = pack2(0.f, 0.f);
#pragma unroll
        for (int m = 0; m < 4; m++) {
            ulonglong2 v = zr[4 * w + m];
            o0 = ffma2(wl[2 * m],     v.x, o0);
            o1 = ffma2(wl[2 * m + 1], v.y, o1);
        }
        float2 s0 = unpk(o0), s1 = unpk(o1);
        float p = (s0.x + s1.x) + prev_sx;   // prev_sx = x-part(T-1)
        p_sm[w][f] = p;
        __syncthreads();
        if (w == 0) {
            float sum = p + p_sm[1][f] + p_sm[2][f] + p_sm[3][f] + ob;
            op[(size_t)(T_LEN - 1) * F_DIM] = tanh_a(sum);
        }
    }
}

// ============================================================================
extern "C" void kernel_launch(void* const* d_in, const int* in_sizes, int n_in,
                              void* d_out, int out_size)
{
    const float* x     = (const float*)d_in[0];
    const float* W_ih  = (const float*)d_in[1];
    const float* W_hh  = (const float*)d_in[2];
    const float* b_ih  = (const float*)d_in[3];
    const float* b_hh  = (const float*)d_in[4];
    const float* W_lin = (const float*)d_in[5];
    const float* b_lin = (const float*)d_in[6];
    float* out = (float*)d_out;

    lstm_fused<<<B_TOT, 128>>>(x, W_ih, W_hh, b_ih, b_hh, W_lin, b_lin, out);
}